// round 2
// baseline (speedup 1.0000x reference)
#include <cuda_runtime.h>
#include <cuda_bf16.h>
#include <cstdint>

// ============================================================================
// DifferentiableXGB — base-arch (compute_103) implementation.
// GEMM: split[B,400] = x[32768,1024] @ W1^T, via mma.sync m16n8k16 bf16.
// Grid: 256 M-tiles x 2 tree-groups. Each CTA: BM=128 rows, BN=208 cols
// (52 trees), full K=1024. Fused epilogue reduces trees -> weighted[b,4]
// partials in g_part; final kernel combines groups + tiny FC.
// ============================================================================

static constexpr int BTOT  = 32768;
static constexpr int Dk    = 1024;
static constexpr int NPAD  = 416;    // 400 cols padded (pad trees have fw=0)
static constexpr int BN    = 208;    // cols per group (52 trees)
static constexpr int BM    = 128;
static constexpr int KC    = 64;     // k-chunk: 64 bf16 = 128B row (SW128)
static constexpr int NCHUNK= 16;
static constexpr int NT    = 256;

// smem byte offsets
static constexpr int S_BIAS = 0;        // 416 f
static constexpr int S_FW   = 1664;     // 104 f
static constexpr int S_RED  = 4096;     // 128*4 f
static constexpr int S_A0   = 8192;     // 128*128B = 16384
static constexpr int S_A1   = 24576;
static constexpr int S_B0   = 40960;    // 208*128B = 26624
static constexpr int S_B1   = 67584;
static constexpr int S_TOTAL= 94208;

#define SW(o) ((o) ^ (((o) >> 3) & 0x70))

__device__ __align__(16) __nv_bfloat16 g_Wbf[NPAD * Dk];   // 852 KB
__device__ float g_part[2][BTOT][4];                        // 1 MB

// ---------------- asm helpers (all base-arch) ----------------
__device__ __forceinline__ uint32_t smem_u32(const void* p) {
    uint32_t a;
    asm("{ .reg .u64 t; cvta.to.shared.u64 t, %1; cvt.u32.u64 %0, t; }" : "=r"(a) : "l"(p));
    return a;
}
__device__ __forceinline__ void ldsm_x4(uint32_t (&r)[4], uint32_t addr) {
    asm volatile("ldmatrix.sync.aligned.m8n8.x4.shared.b16 {%0,%1,%2,%3}, [%4];"
                 : "=r"(r[0]), "=r"(r[1]), "=r"(r[2]), "=r"(r[3]) : "r"(addr));
}
__device__ __forceinline__ void ldsm_x2(uint32_t (&r)[2], uint32_t addr) {
    asm volatile("ldmatrix.sync.aligned.m8n8.x2.shared.b16 {%0,%1}, [%2];"
                 : "=r"(r[0]), "=r"(r[1]) : "r"(addr));
}
__device__ __forceinline__ void mma16816(float (&c)[4], const uint32_t (&a)[4],
                                         uint32_t b0, uint32_t b1) {
    asm volatile("mma.sync.aligned.m16n8k16.row.col.f32.bf16.bf16.f32 "
                 "{%0,%1,%2,%3}, {%4,%5,%6,%7}, {%8,%9}, {%0,%1,%2,%3};"
                 : "+f"(c[0]), "+f"(c[1]), "+f"(c[2]), "+f"(c[3])
                 : "r"(a[0]), "r"(a[1]), "r"(a[2]), "r"(a[3]), "r"(b0), "r"(b1));
}
__device__ __forceinline__ void cp16(uint32_t dst, const void* src) {
    asm volatile("cp.async.cg.shared.global [%0], [%1], 16;" :: "r"(dst), "l"(src));
}
__device__ __forceinline__ float sig_t(float v) {   // sigmoid via 1 MUFU (tanh)
    float t;
    asm("tanh.approx.f32 %0, %1;" : "=f"(t) : "f"(v * 0.5f));
    return fmaf(t, 0.5f, 0.5f);
}

// ---------------- kernel 1: W1 fp32 -> bf16 (padded to 416 rows) ------------
__global__ void xgb_conv_w(const float* __restrict__ W1) {
    int idx = blockIdx.x * 256 + threadIdx.x;      // 416*256 = 106496 uint2
    uint2 o = make_uint2(0u, 0u);
    if (idx < 102400) {                            // 400*1024/4
        float4 v = reinterpret_cast<const float4*>(W1)[idx];
        __nv_bfloat162 p0 = __float22bfloat162_rn(make_float2(v.x, v.y));
        __nv_bfloat162 p1 = __float22bfloat162_rn(make_float2(v.z, v.w));
        o.x = *reinterpret_cast<uint32_t*>(&p0);
        o.y = *reinterpret_cast<uint32_t*>(&p1);
    }
    reinterpret_cast<uint2*>(g_Wbf)[idx] = o;
}

// ---------------- kernel 2: GEMM + fused tree epilogue ----------------------
__global__ void __launch_bounds__(NT, 1)
xgb_main(const float* __restrict__ x, const float* __restrict__ b1,
         const float* __restrict__ fw) {
    extern __shared__ char smem[];
    const uint32_t smb = smem_u32(smem);
    const int tid  = threadIdx.x;
    const int lane = tid & 31;
    const int wid  = tid >> 5;
    const int warpM = wid & 3, warpN = wid >> 2;
    const int g     = blockIdx.x & 1;
    const int row0  = (blockIdx.x >> 1) * BM;

    // constants to smem
    float* bias_sm = reinterpret_cast<float*>(smem + S_BIAS);
    float* fw_sm   = reinterpret_cast<float*>(smem + S_FW);
    for (int i = tid; i < NPAD; i += NT) bias_sm[i] = (i < 400) ? b1[i] : 0.0f;
    if (tid < 104) fw_sm[tid] = (tid < 100) ? fw[tid] : 0.0f;

    const __nv_bfloat16* wsrc = g_Wbf + (size_t)g * BN * Dk;

    // ---- prologue: chunk 0 ----
    float4 av[8];
    {
        const float* xb = x + (size_t)(row0 + (tid >> 4)) * Dk + (tid & 15) * 4;
        #pragma unroll
        for (int r = 0; r < 8; ++r)
            av[r] = *reinterpret_cast<const float4*>(xb + (size_t)r * 16 * Dk);
    }
    for (int i = tid; i < BN * 8; i += NT) {           // B chunk 0 -> buf0
        const int row = i >> 3, c16 = i & 7;
        const uint32_t off = (uint32_t)(row * 128 + c16 * 16);
        cp16(smb + S_B0 + SW(off), wsrc + (size_t)row * Dk + c16 * 8);
    }
    asm volatile("cp.async.commit_group;" ::: "memory");
    {   // A chunk 0 -> buf0
        const int f4 = tid & 15, rb = tid >> 4;
        #pragma unroll
        for (int r = 0; r < 8; ++r) {
            __nv_bfloat162 p0 = __float22bfloat162_rn(make_float2(av[r].x, av[r].y));
            __nv_bfloat162 p1 = __float22bfloat162_rn(make_float2(av[r].z, av[r].w));
            uint2 val;
            val.x = *reinterpret_cast<uint32_t*>(&p0);
            val.y = *reinterpret_cast<uint32_t*>(&p1);
            const uint32_t off = (uint32_t)((rb + 16 * r) * 128 + f4 * 8);
            *reinterpret_cast<uint2*>(smem + S_A0 + SW(off)) = val;
        }
    }

    float acc[2][13][4];
    #pragma unroll
    for (int j = 0; j < 2; ++j)
        #pragma unroll
        for (int b = 0; b < 13; ++b)
            #pragma unroll
            for (int k = 0; k < 4; ++k) acc[j][b][k] = 0.0f;

    // ---- main K loop ----
    for (int c = 0; c < NCHUNK; ++c) {
        const uint32_t sA = (c & 1) ? S_A1 : S_A0;
        const uint32_t sB = (c & 1) ? S_B1 : S_B0;
        asm volatile("cp.async.wait_group 0;" ::: "memory");
        __syncthreads();                                    // buf c ready

        if (c + 1 < NCHUNK) {                               // prefetch c+1
            const float* xb = x + (size_t)(row0 + (tid >> 4)) * Dk
                              + (c + 1) * KC + (tid & 15) * 4;
            #pragma unroll
            for (int r = 0; r < 8; ++r)
                av[r] = *reinterpret_cast<const float4*>(xb + (size_t)r * 16 * Dk);
            const uint32_t sBn = (c & 1) ? S_B0 : S_B1;
            const __nv_bfloat16* ws = wsrc + (c + 1) * KC;
            for (int i = tid; i < BN * 8; i += NT) {
                const int row = i >> 3, c16 = i & 7;
                const uint32_t off = (uint32_t)(row * 128 + c16 * 16);
                cp16(smb + sBn + SW(off), ws + (size_t)row * Dk + c16 * 8);
            }
            asm volatile("cp.async.commit_group;" ::: "memory");
        }

        // compute chunk c
        #pragma unroll
        for (int ks = 0; ks < 4; ++ks) {
            uint32_t a[2][4];
            #pragma unroll
            for (int j = 0; j < 2; ++j) {
                const uint32_t off = (uint32_t)((warpM * 32 + j * 16 + (lane & 15)) * 128
                                     + ks * 32 + ((lane >> 4) << 4));
                ldsm_x4(a[j], smb + sA + SW(off));
            }
            #pragma unroll
            for (int p = 0; p < 6; ++p) {
                uint32_t bq[4];
                const uint32_t rowb = (uint32_t)(warpN * 104 + p * 16 + (lane & 7)
                                     + ((lane >> 4) << 3));
                const uint32_t off = rowb * 128 + ks * 32 + (((lane >> 3) & 1) << 4);
                ldsm_x4(bq, smb + sB + SW(off));
                mma16816(acc[0][2 * p],     a[0], bq[0], bq[1]);
                mma16816(acc[0][2 * p + 1], a[0], bq[2], bq[3]);
                mma16816(acc[1][2 * p],     a[1], bq[0], bq[1]);
                mma16816(acc[1][2 * p + 1], a[1], bq[2], bq[3]);
            }
            {   // last n8 block (12)
                uint32_t b2[2];
                const uint32_t rowb = (uint32_t)(warpN * 104 + 96 + (lane & 7));
                const uint32_t off = rowb * 128 + ks * 32 + (((lane >> 3) & 1) << 4);
                ldsm_x2(b2, smb + sB + SW(off));
                mma16816(acc[0][12], a[0], b2[0], b2[1]);
                mma16816(acc[1][12], a[1], b2[0], b2[1]);
            }
        }

        if (c + 1 < NCHUNK) {
            __syncthreads();                       // all warps done with buf c-1
            const uint32_t sAn = (c & 1) ? S_A0 : S_A1;
            const int f4 = tid & 15, rb = tid >> 4;
            #pragma unroll
            for (int r = 0; r < 8; ++r) {
                __nv_bfloat162 p0 = __float22bfloat162_rn(make_float2(av[r].x, av[r].y));
                __nv_bfloat162 p1 = __float22bfloat162_rn(make_float2(av[r].z, av[r].w));
                uint2 val;
                val.x = *reinterpret_cast<uint32_t*>(&p0);
                val.y = *reinterpret_cast<uint32_t*>(&p1);
                const uint32_t off = (uint32_t)((rb + 16 * r) * 128 + f4 * 8);
                *reinterpret_cast<uint2*>(smem + sAn + SW(off)) = val;
            }
        }
    }

    // ---- fused epilogue: trees -> weighted[row, 0..3] partials ----
    const int q  = lane & 3;     // col quad within n8 block
    const int rq = lane >> 2;    // row within 8
    float wac[4][2] = {{0.f,0.f},{0.f,0.f},{0.f,0.f},{0.f,0.f}};
    #pragma unroll
    for (int j = 0; j < 2; ++j) {
        #pragma unroll
        for (int b = 0; b < 13; ++b) {
            const int cg = g * BN + warpN * 104 + b * 8 + q * 2;
            const float bias0 = bias_sm[cg], bias1 = bias_sm[cg + 1];
            const float fwv = fw_sm[cg >> 2];
            #pragma unroll
            for (int h = 0; h < 2; ++h) {
                const float s0 = acc[j][b][2 * h]     + bias0;
                const float s1 = acc[j][b][2 * h + 1] + bias1;
                const float sp = s0 + s1;
                const float S  = sp + __shfl_xor_sync(0xffffffffu, sp, 1);
                const float wS = fwv * S;
                wac[j * 2 + h][0] = fmaf(wS, sig_t(s0), wac[j * 2 + h][0]);
                wac[j * 2 + h][1] = fmaf(wS, sig_t(s1), wac[j * 2 + h][1]);
            }
        }
    }
    #pragma unroll
    for (int s = 0; s < 4; ++s) {        // combine tree halves (lanes q ^ 2)
        wac[s][0] += __shfl_xor_sync(0xffffffffu, wac[s][0], 2);
        wac[s][1] += __shfl_xor_sync(0xffffffffu, wac[s][1], 2);
    }
    float* red = reinterpret_cast<float*>(smem + S_RED);
    __syncthreads();                      // A/B buffers done; reuse smem region
    if (warpN == 1 && q < 2) {
        #pragma unroll
        for (int s = 0; s < 4; ++s) {
            const int rl = warpM * 32 + (s >> 1) * 16 + (s & 1) * 8 + rq;
            red[rl * 4 + q * 2]     = wac[s][0];
            red[rl * 4 + q * 2 + 1] = wac[s][1];
        }
    }
    __syncthreads();
    if (warpN == 0 && q < 2) {
        #pragma unroll
        for (int s = 0; s < 4; ++s) {
            const int rl = warpM * 32 + (s >> 1) * 16 + (s & 1) * 8 + rq;
            float2 v;
            v.x = wac[s][0] + red[rl * 4 + q * 2];
            v.y = wac[s][1] + red[rl * 4 + q * 2 + 1];
            *reinterpret_cast<float2*>(&g_part[g][row0 + rl][q * 2]) = v;
        }
    }
}

// ---------------- kernel 3: combine groups + FC -----------------------------
__global__ void xgb_final(const float* __restrict__ fcw, const float* __restrict__ fcb,
                          float* __restrict__ out) {
    const int r = blockIdx.x * 256 + threadIdx.x;
    float4 a = *reinterpret_cast<const float4*>(&g_part[0][r][0]);
    float4 b = *reinterpret_cast<const float4*>(&g_part[1][r][0]);
    const float w0 = a.x + b.x, w1 = a.y + b.y, w2 = a.z + b.z, w3 = a.w + b.w;
    float2 o;
    o.x = fcb[0] + w0 * fcw[0] + w1 * fcw[1] + w2 * fcw[2] + w3 * fcw[3];
    o.y = fcb[1] + w0 * fcw[4] + w1 * fcw[5] + w2 * fcw[6] + w3 * fcw[7];
    *reinterpret_cast<float2*>(out + 2 * r) = o;
}

// ---------------- launch ----------------------------------------------------
extern "C" void kernel_launch(void* const* d_in, const int* in_sizes, int n_in,
                              void* d_out, int out_size) {
    const float* x   = (const float*)d_in[0];
    const float* W1  = (const float*)d_in[1];
    const float* b1  = (const float*)d_in[2];
    const float* fw  = (const float*)d_in[3];
    const float* fcw = (const float*)d_in[4];
    const float* fcb = (const float*)d_in[5];
    float* out = (float*)d_out;

    cudaFuncSetAttribute(xgb_main, cudaFuncAttributeMaxDynamicSharedMemorySize, S_TOTAL);

    xgb_conv_w<<<416, 256>>>(W1);
    xgb_main<<<(BTOT / BM) * 2, NT, S_TOTAL>>>(x, b1, fw);
    xgb_final<<<BTOT / 256, 256>>>(fcw, fcb, out);
}